// round 8
// baseline (speedup 1.0000x reference)
#include <cuda_runtime.h>
#include <cuda_fp16.h>

namespace {
constexpr int H = 128, Wd = 128;
constexpr int PLANE = H * Wd;                       // 16384
constexpr int NPLANES = 32 * 64;                    // 2048
constexpr long long TOTROWS = (long long)NPLANES * H;  // 262144
constexpr int NBLK = 444;                           // 3 CTAs/SM on 148 SMs
constexpr int NWARP = NBLK * 10;                    // 4440 warp strips
constexpr int PAIR_BYTES = 375 * 32 * 4;            // 48000
constexpr int SING_BYTES = 75 * 32 * 4;             // 9600
constexpr int SMEM_BYTES = PAIR_BYTES + SING_BYTES; // 57600
}

struct RowS {
    float x[6];   // [0]=left edge, [1..4]=own 4 cols, [5]=right edge
    int   b[6];   // bins
};

__device__ __forceinline__ float4 ldrow(const float* __restrict__ xp, int r,
                                        int lane) {
    float4 v = make_float4(0.f, 0.f, 0.f, 0.f);
    if ((unsigned)r < (unsigned)H)
        v = __ldg(reinterpret_cast<const float4*>(xp + r * Wd + lane * 4));
    return v;
}

__device__ __forceinline__ int quant(float x) {
    return (int)fminf(x * 5.0f, 4.0f);          // x>=0; floor==trunc
}

// Quantize + edge exchange (2 MIO ops; edge bins recomputed on fma pipe).
__device__ __forceinline__ void build(float4 v, int lane, RowS& R) {
    R.x[1] = v.x; R.x[2] = v.y; R.x[3] = v.z; R.x[4] = v.w;
#pragma unroll
    for (int i = 1; i <= 4; ++i) R.b[i] = quant(R.x[i]);
    R.x[0] = __shfl_up_sync(0xffffffffu, v.w, 1);
    R.x[5] = __shfl_down_sync(0xffffffffu, v.x, 1);
    if (lane == 0)  R.x[0] = 0.f;   // x=0 kills the term; b irrelevant
    if (lane == 31) R.x[5] = 0.f;
    R.b[0] = quant(R.x[0]);
    R.b[5] = quant(R.x[5]);
}

__global__ __launch_bounds__(320, 3)
void col_kernel(const float* __restrict__ x,
                const float* __restrict__ Wp,
                const float* __restrict__ Lp,
                float* __restrict__ out) {
    extern __shared__ char smem[];
    // Pair table (fp16x2), bank-replicated 32x:
    //   addr = lane*4 + bp*128 + bq1*640 + bq0*3200 + rp*16000
    //   entry = ( W[rp,0]*L[bq0,bp] , W[rp,1]*L[bq1,bp] )
    __half2* sP = reinterpret_cast<__half2*>(smem);
    // Singles table (fp32), bank-replicated 32x:
    //   addr = lane*4 + bp*128 + bq*640 + rp*3200 ; entry = W[rp,2]*L[bq,bp]
    float* sS = reinterpret_cast<float*>(smem + PAIR_BYTES);

    for (int t = threadIdx.x; t < 375 * 32; t += 320) {
        int idx = t >> 5;
        int rp  = idx / 125;
        int rem = idx - rp * 125;
        int bq0 = rem / 25;  int r2 = rem - bq0 * 25;
        int bq1 = r2 / 5;    int bp = r2 - bq1 * 5;
        float w0 = Wp[rp * 3 + 0] * Lp[bq0 * 5 + bp];
        float w1 = Wp[rp * 3 + 1] * Lp[bq1 * 5 + bp];
        sP[t] = __floats2half2_rn(w0, w1);
    }
    for (int t = threadIdx.x; t < 75 * 32; t += 320) {
        int idx = t >> 5;                 // rp*25 + bq*5 + bp
        int rp  = idx / 25;
        int i   = idx - rp * 25;
        sS[t] = Wp[rp * 3 + 2] * Lp[i];
    }
    __syncthreads();

    const int lane = threadIdx.x & 31;
    const int gw   = blockIdx.x * 10 + (threadIdx.x >> 5);
    const char* pairBase = reinterpret_cast<const char*>(sP) + lane * 4;
    const char* singBase = reinterpret_cast<const char*>(sS) + lane * 4;

    // Contiguous global-row strip for this warp.
    long long gs = (long long)gw * TOTROWS / NWARP;
    long long ge = (long long)(gw + 1) * TOTROWS / NWARP;

    long long s = gs;
    while (s < ge) {
        const int p  = (int)(s >> 7);
        const int rs = (int)(s & 127);
        const int re = min(H, rs + (int)(ge - s));     // segment = one plane
        const float* xp = x + (size_t)p * PLANE;
        float* op = out + (size_t)p * PLANE;

        RowS Rr[3];
        float4 wv[3];
        build(ldrow(xp, rs - 1, lane), lane, Rr[0]);
        build(ldrow(xp, rs,     lane), lane, Rr[1]);
        wv[2] = ldrow(xp, rs + 1, lane);

        // 3-row blocks; all rotation indices static.
        for (int k = rs; k < re; k += 3) {
#pragma unroll
            for (int j = 0; j < 3; ++j) {
                const int r = k + j;
                wv[j] = ldrow(xp, r + 2, lane);            // prefetch
                build(wv[(j + 2) % 3], lane, Rr[(j + 2) % 3]);

                const RowS& A  = Rr[j % 3];
                const RowS& Bc = Rr[(j + 1) % 3];
                const RowS& Cn = Rr[(j + 2) % 3];

                float res[4];
#pragma unroll
                for (int i = 0; i < 4; ++i) {
                    const int bp = Bc.b[i + 1];
                    const char* pbP = pairBase + bp * 128;
                    const char* pbS = singBase + bp * 128;
                    float sacc = 0.f;
#define COL_PAIR(R, rp)                                                        \
                    {                                                          \
                        __half2 pr = *reinterpret_cast<const __half2*>(        \
                            pbP + (R).b[i] * 3200 + (R).b[i + 1] * 640 +       \
                            (rp) * 16000);                                     \
                        float2 w = __half22float2(pr);                         \
                        sacc += w.x * (R).x[i] + w.y * (R).x[i + 1];           \
                    }
#define COL_SING(R, rp)                                                        \
                    sacc += *reinterpret_cast<const float*>(                   \
                                pbS + (R).b[i + 2] * 640 + (rp) * 3200)        \
                            * (R).x[i + 2];
                    COL_PAIR(A, 0)  COL_PAIR(Bc, 1) COL_PAIR(Cn, 2)
                    COL_SING(A, 0)  COL_SING(Bc, 1) COL_SING(Cn, 2)
#undef COL_PAIR
#undef COL_SING
                    res[i] = sacc;
                }

                if (j == 0 || r < re)
                    *reinterpret_cast<float4*>(op + r * Wd + lane * 4) =
                        make_float4(res[0], res[1], res[2], res[3]);
            }
        }
        s += re - rs;
    }
}

extern "C" void kernel_launch(void* const* d_in, const int* in_sizes, int n_in,
                              void* d_out, int out_size) {
    const float* x = nullptr;
    const float* W = nullptr;
    const float* L = nullptr;
    for (int i = 0; i < n_in; ++i) {
        if (in_sizes[i] == 9)       W = (const float*)d_in[i];
        else if (in_sizes[i] == 25) L = (const float*)d_in[i];
        else                        x = (const float*)d_in[i];
    }
    cudaFuncSetAttribute(col_kernel,
                         cudaFuncAttributeMaxDynamicSharedMemorySize,
                         SMEM_BYTES);
    col_kernel<<<NBLK, 320, SMEM_BYTES>>>(x, W, L, (float*)d_out);
}

// round 9
// speedup vs baseline: 1.0284x; 1.0284x over previous
#include <cuda_runtime.h>

namespace {
constexpr int H = 128, Wd = 128;
constexpr int PLANE = H * Wd;                       // 16384
constexpr int NPLANES = 32 * 64;                    // 2048
constexpr long long TOTROWS = (long long)NPLANES * H;  // 262144
constexpr int NBLK = 740;                           // 5 CTAs/SM on 148 SMs
constexpr int WPB = 7;                              // 224 threads
constexpr int NWARP = NBLK * WPB;                   // 5180 warp strips
}

struct RowS {
    float x[6];   // [0]=left edge, [1..4]=own 4 cols, [5]=right edge
    int   b[6];   // bins
};

__device__ __forceinline__ float4 ldrow(const float* __restrict__ xp, int r,
                                        int lane) {
    float4 v = make_float4(0.f, 0.f, 0.f, 0.f);
    if ((unsigned)r < (unsigned)H)
        v = __ldg(reinterpret_cast<const float4*>(xp + r * Wd + lane * 4));
    return v;
}

__device__ __forceinline__ int quant(float x) {
    return (int)fminf(x * 5.0f, 4.0f);          // x>=0; floor==trunc
}

// Quantize + edge exchange (2 MIO ops; edge bins recomputed on fma pipe).
__device__ __forceinline__ void build(float4 v, int lane, RowS& R) {
    R.x[1] = v.x; R.x[2] = v.y; R.x[3] = v.z; R.x[4] = v.w;
#pragma unroll
    for (int i = 1; i <= 4; ++i) R.b[i] = quant(R.x[i]);
    R.x[0] = __shfl_up_sync(0xffffffffu, v.w, 1);
    R.x[5] = __shfl_down_sync(0xffffffffu, v.x, 1);
    if (lane == 0)  R.x[0] = 0.f;   // x=0 kills the term; b irrelevant
    if (lane == 31) R.x[5] = 0.f;
    R.b[0] = quant(R.x[0]);
    R.b[5] = quant(R.x[5]);
}

__global__ __launch_bounds__(224, 5)
void col_kernel(const float* __restrict__ x,
                const float* __restrict__ Wp,
                const float* __restrict__ Lp,
                float* __restrict__ out) {
    // Bank-replicated WL table: addr = laneBase + bp*128 + bq*640 + o*3200.
    // Lane l only ever touches bank l -> conflict-free LDS.
    __shared__ float sWL[225 * 32];

    for (int t = threadIdx.x; t < 225 * 32; t += 224) {
        int idx = t >> 5;               // o*25 + bq*5 + bp
        int o  = idx / 25;
        int i  = idx - o * 25;          // bq*5 + bp (L row-major: L[bq][bp])
        sWL[t] = Wp[o] * Lp[i];
    }
    __syncthreads();

    const int lane = threadIdx.x & 31;
    const int gw   = blockIdx.x * WPB + (threadIdx.x >> 5);
    const char* laneBase = reinterpret_cast<const char*>(sWL) + lane * 4;

    // Contiguous global-row strip for this warp.
    long long gs = (long long)gw * TOTROWS / NWARP;
    long long ge = (long long)(gw + 1) * TOTROWS / NWARP;

    long long s = gs;
    while (s < ge) {
        const int p  = (int)(s >> 7);
        const int rs = (int)(s & 127);
        const int re = min(H, rs + (int)(ge - s));     // segment = one plane
        const float* xp = x + (size_t)p * PLANE;
        float* op = out + (size_t)p * PLANE;

        RowS Rr[3];
        float4 wv[2];
        build(ldrow(xp, rs - 1, lane), lane, Rr[0]);
        build(ldrow(xp, rs,     lane), lane, Rr[1]);
        wv[1] = ldrow(xp, rs + 1, lane);

        // 6-row unrolled blocks: 2-slot raw ring (load wv[j&1], consume
        // wv[(j+1)&1]) x 3-slot RowS rotation -> all indices static.
        for (int k = rs; k < re; k += 6) {
#pragma unroll
            for (int j = 0; j < 6; ++j) {
                const int r = k + j;
                wv[j & 1] = ldrow(xp, r + 2, lane);        // prefetch
                build(wv[(j + 1) & 1], lane, Rr[(j + 2) % 3]);

                const RowS& A  = Rr[j % 3];
                const RowS& Bc = Rr[(j + 1) % 3];
                const RowS& Cn = Rr[(j + 2) % 3];

                float res[4];
#pragma unroll
                for (int i = 0; i < 4; ++i) {
                    const char* pb = laneBase + Bc.b[i + 1] * 128;
                    float sacc = 0.f;
#define COL_TERM(R, o, dw)                                                     \
                    sacc += *reinterpret_cast<const float*>(                   \
                                pb + (R).b[i + (dw)] * 640 + (o) * 3200)       \
                            * (R).x[i + (dw)];
                    COL_TERM(A,  0, 0) COL_TERM(A,  1, 1) COL_TERM(A,  2, 2)
                    COL_TERM(Bc, 3, 0) COL_TERM(Bc, 4, 1) COL_TERM(Bc, 5, 2)
                    COL_TERM(Cn, 6, 0) COL_TERM(Cn, 7, 1) COL_TERM(Cn, 8, 2)
#undef COL_TERM
                    res[i] = sacc;
                }

                if (j == 0 || r < re)
                    *reinterpret_cast<float4*>(op + r * Wd + lane * 4) =
                        make_float4(res[0], res[1], res[2], res[3]);
            }
        }
        s += re - rs;
    }
}

extern "C" void kernel_launch(void* const* d_in, const int* in_sizes, int n_in,
                              void* d_out, int out_size) {
    const float* x = nullptr;
    const float* W = nullptr;
    const float* L = nullptr;
    for (int i = 0; i < n_in; ++i) {
        if (in_sizes[i] == 9)       W = (const float*)d_in[i];
        else if (in_sizes[i] == 25) L = (const float*)d_in[i];
        else                        x = (const float*)d_in[i];
    }
    col_kernel<<<NBLK, 224>>>(x, W, L, (float*)d_out);
}

// round 10
// speedup vs baseline: 1.3564x; 1.3190x over previous
#include <cuda_runtime.h>

namespace {
constexpr int H = 128, Wd = 128;
constexpr int PLANE = H * Wd;                       // 16384
constexpr int NPLANES = 32 * 64;                    // 2048
constexpr long long TOTROWS = (long long)NPLANES * H;  // 262144
constexpr int NBLK = 608;                           // 4 CTAs/SM x 152 SMs
constexpr int NWARP = NBLK * 8;                     // 4864 warp strips
}

struct RowS {
    float x[6];   // [0]=left edge, [1..4]=own 4 cols, [5]=right edge
    int   b[6];   // bins
};

__device__ __forceinline__ float4 ldrow(const float* __restrict__ xp, int r,
                                        int lane) {
    float4 v = make_float4(0.f, 0.f, 0.f, 0.f);
    if ((unsigned)r < (unsigned)H)
        v = __ldg(reinterpret_cast<const float4*>(xp + r * Wd + lane * 4));
    return v;
}

__device__ __forceinline__ int quant(float x) {
    return (int)fminf(x * 5.0f, 4.0f);          // x>=0; floor==trunc
}

// Quantize + edge exchange (2 MIO ops; edge bins recomputed on fma pipe).
__device__ __forceinline__ void build(float4 v, int lane, RowS& R) {
    R.x[1] = v.x; R.x[2] = v.y; R.x[3] = v.z; R.x[4] = v.w;
#pragma unroll
    for (int i = 1; i <= 4; ++i) R.b[i] = quant(R.x[i]);
    R.x[0] = __shfl_up_sync(0xffffffffu, v.w, 1);
    R.x[5] = __shfl_down_sync(0xffffffffu, v.x, 1);
    if (lane == 0)  R.x[0] = 0.f;   // x=0 kills the term; b irrelevant
    if (lane == 31) R.x[5] = 0.f;
    R.b[0] = quant(R.x[0]);
    R.b[5] = quant(R.x[5]);
}

__global__ __launch_bounds__(256, 4)
void col_kernel(const float* __restrict__ x,
                const float* __restrict__ Wp,
                const float* __restrict__ Lp,
                float* __restrict__ out) {
    // Bank-replicated WL table: addr = laneBase + bp*128 + bq*640 + o*3200.
    // Lane l only ever touches bank l -> conflict-free LDS.
    __shared__ float sWL[225 * 32];

    for (int t = threadIdx.x; t < 225 * 32; t += 256) {
        int idx = t >> 5;               // o*25 + bq*5 + bp
        int o  = idx / 25;
        int i  = idx - o * 25;          // bq*5 + bp (L row-major: L[bq][bp])
        sWL[t] = Wp[o] * Lp[i];
    }
    __syncthreads();

    const int lane = threadIdx.x & 31;
    const int gw   = blockIdx.x * 8 + (threadIdx.x >> 5);
    const char* laneBase = reinterpret_cast<const char*>(sWL) + lane * 4;

    // Contiguous global-row strip for this warp.
    long long gs = (long long)gw * TOTROWS / NWARP;
    long long ge = (long long)(gw + 1) * TOTROWS / NWARP;

    long long s = gs;
    while (s < ge) {
        const int p  = (int)(s >> 7);
        const int rs = (int)(s & 127);
        const int re = min(H, rs + (int)(ge - s));     // segment = one plane
        const float* xp = x + (size_t)p * PLANE;
        float* op = out + (size_t)p * PLANE;

        RowS Rr[3];
        float4 wv[3];
        build(ldrow(xp, rs - 1, lane), lane, Rr[0]);
        build(ldrow(xp, rs,     lane), lane, Rr[1]);
        wv[0] = ldrow(xp, rs + 1, lane);               // raw row rs+1
        wv[1] = ldrow(xp, rs + 2, lane);               // raw row rs+2

        // 3-row blocks, 2-iteration-deep LDG pipeline. Invariant at iter j
        // (row r): Rr holds r-1, r; wv[j%3] holds raw r+1; wv[(j+1)%3]
        // holds raw r+2 (in flight); we issue the load of r+3 first.
        for (int k = rs; k < re; k += 3) {
#pragma unroll
            for (int j = 0; j < 3; ++j) {
                const int r = k + j;
                wv[(j + 2) % 3] = ldrow(xp, r + 3, lane);   // deep prefetch
                build(wv[j % 3], lane, Rr[(j + 2) % 3]);    // row r+1

                const RowS& A  = Rr[j % 3];
                const RowS& Bc = Rr[(j + 1) % 3];
                const RowS& Cn = Rr[(j + 2) % 3];

                float res[4];
#pragma unroll
                for (int i = 0; i < 4; ++i) {
                    const char* pb = laneBase + Bc.b[i + 1] * 128;
                    float sacc = 0.f;
#define COL_TERM(R, o, dw)                                                     \
                    sacc += *reinterpret_cast<const float*>(                   \
                                pb + (R).b[i + (dw)] * 640 + (o) * 3200)       \
                            * (R).x[i + (dw)];
                    COL_TERM(A,  0, 0) COL_TERM(A,  1, 1) COL_TERM(A,  2, 2)
                    COL_TERM(Bc, 3, 0) COL_TERM(Bc, 4, 1) COL_TERM(Bc, 5, 2)
                    COL_TERM(Cn, 6, 0) COL_TERM(Cn, 7, 1) COL_TERM(Cn, 8, 2)
#undef COL_TERM
                    res[i] = sacc;
                }

                if (j == 0 || r < re)
                    *reinterpret_cast<float4*>(op + r * Wd + lane * 4) =
                        make_float4(res[0], res[1], res[2], res[3]);
            }
        }
        s += re - rs;
    }
}

extern "C" void kernel_launch(void* const* d_in, const int* in_sizes, int n_in,
                              void* d_out, int out_size) {
    const float* x = nullptr;
    const float* W = nullptr;
    const float* L = nullptr;
    for (int i = 0; i < n_in; ++i) {
        if (in_sizes[i] == 9)       W = (const float*)d_in[i];
        else if (in_sizes[i] == 25) L = (const float*)d_in[i];
        else                        x = (const float*)d_in[i];
    }
    col_kernel<<<NBLK, 256>>>(x, W, L, (float*)d_out);
}